// round 9
// baseline (speedup 1.0000x reference)
#include <cuda_runtime.h>
#include <math.h>

#define LAYERS 2
#define BB 8
#define TT 512
#define HH 128
#define MM (BB*TT)   // 4096 rows

// ---------------- device scratch ----------------
__device__ float  g_Wt[LAYERS][6][HH*HH];  // transposed weights [l][p][d][h]
__device__ float  g_q[MM*HH];              // q
__device__ float  g_k[MM*HH];              // k / sqrt(H)
__device__ float  g_i[MM*HH];              // exp(i)   (planar, for den warp)
__device__ float  g_f[MM*HH];              // sigm(f)  (planar, for den warp)
__device__ float4 g_gates[MM*HH];          // packed (i, f, v, o) per (m, h)
__device__ float  g_h[MM*HH];              // UNNORMALIZED hidden (o * C.q)
__device__ float  g_rden[MM];              // 1 / max(|n.q|, 1) per (b,t)

// ---------------- weight transpose ----------------
__global__ void transpose_w_kernel(const float* __restrict__ Wq, const float* __restrict__ Wk,
                                   const float* __restrict__ Wv, const float* __restrict__ Wi,
                                   const float* __restrict__ Wf, const float* __restrict__ Wo)
{
    int idx = blockIdx.x * blockDim.x + threadIdx.x;
    const int total = LAYERS * 6 * HH * HH;
    if (idx >= total) return;
    int l   = idx / (6 * HH * HH);
    int rem = idx - l * 6 * HH * HH;
    int p   = rem / (HH * HH);
    int e   = rem - p * (HH * HH);
    int d   = e >> 7;
    int h   = e & 127;
    const float* W = (p == 0) ? Wq : (p == 1) ? Wk : (p == 2) ? Wv
                   : (p == 3) ? Wi : (p == 4) ? Wf : Wo;
    g_Wt[l][p][d * HH + h] = W[l * HH * HH + h * HH + d];
}

// ---------------- projection GEMM + bias + activation ----------------
// 64x128 tile, BK=8, DOUBLE-BUFFERED smem, 128 threads, 8x8 microtile.
// grid (MM/64, 6) = 384 CTAs. Next k-block's LDGs staged in registers during
// the FMA block; one __syncthreads per k-block.
// For layer 1 (X==nullptr) the A operand is g_h scaled by g_rden (fused norm).
__global__ __launch_bounds__(128) void proj_gemm_kernel(
    const float* __restrict__ X, int layer,
    const float* __restrict__ bq, const float* __restrict__ bk,
    const float* __restrict__ bv, const float* __restrict__ bi,
    const float* __restrict__ bf, const float* __restrict__ bo)
{
    const float* __restrict__ Xp = X ? X : g_h;
    const int p  = blockIdx.y;
    const int m0 = blockIdx.x * 64;
    const float* __restrict__ Wt = g_Wt[layer][p];

    __shared__ float As[2][8][64];
    __shared__ float Bs[2][8][128];

    const int tid = threadIdx.x;
    const int tx = tid & 15;          // 16 col groups (x8 = 128)
    const int ty = tid >> 4;          // 8 row groups  (x8 = 64)
    const int lm = tid >> 1;          // 0..63 : M row for X load
    const int lk = (tid & 1) << 2;    // 0 or 4
    const int wh = (tid & 15) << 3;   // 0..120
    const int wk = tid >> 4;          // 0..7

    const float rd = X ? 1.0f : g_rden[m0 + lm];  // fused normalization of layer-0 output

    // preload k-block 0 into buffer 0
    float4 xa = *(const float4*)(Xp + (m0 + lm) * HH + lk);
    float4 wa = *(const float4*)(Wt + wk * HH + wh);
    float4 wb = *(const float4*)(Wt + wk * HH + wh + 4);
    As[0][lk + 0][lm] = xa.x * rd;
    As[0][lk + 1][lm] = xa.y * rd;
    As[0][lk + 2][lm] = xa.z * rd;
    As[0][lk + 3][lm] = xa.w * rd;
    *(float4*)(&Bs[0][wk][wh])     = wa;
    *(float4*)(&Bs[0][wk][wh + 4]) = wb;
    __syncthreads();

    float acc[8][8];
    #pragma unroll
    for (int i = 0; i < 8; i++)
        #pragma unroll
        for (int j = 0; j < 8; j++) acc[i][j] = 0.0f;

    #pragma unroll
    for (int kb = 0; kb < 16; kb++) {
        const int cur = kb & 1, nxt = cur ^ 1;
        if (kb < 15) {
            const int k0 = (kb + 1) * 8;
            xa = *(const float4*)(Xp + (m0 + lm) * HH + k0 + lk);
            wa = *(const float4*)(Wt + (k0 + wk) * HH + wh);
            wb = *(const float4*)(Wt + (k0 + wk) * HH + wh + 4);
        }
        #pragma unroll
        for (int kk = 0; kk < 8; kk++) {
            float a[8], b[8];
            *(float4*)(a)     = *(const float4*)(&As[cur][kk][ty * 8]);
            *(float4*)(a + 4) = *(const float4*)(&As[cur][kk][ty * 8 + 4]);
            *(float4*)(b)     = *(const float4*)(&Bs[cur][kk][tx * 8]);
            *(float4*)(b + 4) = *(const float4*)(&Bs[cur][kk][tx * 8 + 4]);
            #pragma unroll
            for (int i = 0; i < 8; i++)
                #pragma unroll
                for (int j = 0; j < 8; j++)
                    acc[i][j] = fmaf(a[i], b[j], acc[i][j]);
        }
        if (kb < 15) {
            As[nxt][lk + 0][lm] = xa.x * rd;
            As[nxt][lk + 1][lm] = xa.y * rd;
            As[nxt][lk + 2][lm] = xa.z * rd;
            As[nxt][lk + 3][lm] = xa.w * rd;
            *(float4*)(&Bs[nxt][wk][wh])     = wa;
            *(float4*)(&Bs[nxt][wk][wh + 4]) = wb;
        }
        __syncthreads();
    }

    const float* __restrict__ bias =
        (p == 0) ? bq : (p == 1) ? bk : (p == 2) ? bv
      : (p == 3) ? bi : (p == 4) ? bf : bo;
    const float kscale = 0.088388347648318447f;  // 1/sqrt(128)

    #pragma unroll
    for (int i = 0; i < 8; i++) {
        const int m = m0 + ty * 8 + i;
        #pragma unroll
        for (int j = 0; j < 8; j++) {
            const int h = tx * 8 + j;
            float v = acc[i][j] + bias[layer * HH + h];
            const int e = m * HH + h;
            if (p == 0) {
                g_q[e] = v;
            } else if (p == 1) {
                g_k[e] = v * kscale;
            } else if (p == 2) {
                g_gates[e].z = v;                       // v
            } else if (p == 3) {
                v = expf(v);
                g_i[e] = v; g_gates[e].x = v;           // i
            } else if (p == 4) {
                v = 1.0f / (1.0f + expf(-v));
                g_f[e] = v; g_gates[e].y = v;           // f
            } else {
                v = 1.0f / (1.0f + expf(-v));
                g_gates[e].w = v;                       // o
            }
        }
    }
}

// ---------------- barrier-free mLSTM scan ----------------
// grid (17, 8), block 256 (8 warps).
//  bx < 16 : row CTAs. Warp w owns row r = bx*8 + w of batch b.
//            Lane owns C[r][c4..c4+3]. Per step: LDG q4/k4 (lane-varying) +
//            one broadcast packed-gate float4. NO smem, NO __syncthreads.
//            h_tilde partials batch-reduced 8 steps at a time (independent
//            shuffle chains). Output written UNNORMALIZED (o * C.q).
//  bx == 16: warp 0 computes the denominator recurrence n_t = f*n + i*k and
//            stores rden[b][t] = 1/max(|n_{t-1}.q_t|, 1).
__global__ __launch_bounds__(256) void scan_kernel()
{
    const int b    = blockIdx.y;
    const int w    = threadIdx.x >> 5;
    const int lane = threadIdx.x & 31;
    const int c4   = lane << 2;

    if (blockIdx.x == 16) {
        // ---- denominator warp ----
        if (w != 0) return;
        const float* __restrict__ Pq = g_q + b * TT * HH + c4;
        const float* __restrict__ Pk = g_k + b * TT * HH + c4;
        const float* __restrict__ Pi = g_i + b * TT * HH + c4;
        const float* __restrict__ Pf = g_f + b * TT * HH + c4;
        float* __restrict__ Dr = g_rden + b * TT;

        float4 qb[8], kb[8], ib[8], fb[8];
        #pragma unroll
        for (int s = 0; s < 8; s++) {
            qb[s] = *(const float4*)(Pq + s * HH);
            kb[s] = *(const float4*)(Pk + s * HH);
            ib[s] = *(const float4*)(Pi + s * HH);
            fb[s] = *(const float4*)(Pf + s * HH);
        }
        float n0 = 0.f, n1 = 0.f, n2 = 0.f, n3 = 0.f;

        for (int gI = 0; gI < 64; gI++) {
            float pd[8];
            #pragma unroll
            for (int s = 0; s < 8; s++) {
                float4 q = qb[s], k = kb[s], ii = ib[s], ff = fb[s];
                pd[s] = n0 * q.x + n1 * q.y + n2 * q.z + n3 * q.w;  // uses OLD n
                n0 = fmaf(ff.x, n0, ii.x * k.x);
                n1 = fmaf(ff.y, n1, ii.y * k.y);
                n2 = fmaf(ff.z, n2, ii.z * k.z);
                n3 = fmaf(ff.w, n3, ii.w * k.w);
                if (gI < 63) {
                    const int off = (gI * 8 + s + 8) * HH;
                    qb[s] = *(const float4*)(Pq + off);
                    kb[s] = *(const float4*)(Pk + off);
                    ib[s] = *(const float4*)(Pi + off);
                    fb[s] = *(const float4*)(Pf + off);
                }
            }
            #pragma unroll
            for (int o = 16; o > 0; o >>= 1)
                #pragma unroll
                for (int s = 0; s < 8; s++)
                    pd[s] += __shfl_xor_sync(0xffffffffu, pd[s], o);
            if (lane == 0) {
                #pragma unroll
                for (int s = 0; s < 8; s++)
                    Dr[gI * 8 + s] = 1.0f / fmaxf(fabsf(pd[s]), 1.0f);
            }
        }
        return;
    }

    // ---- row warps ----
    const int r = blockIdx.x * 8 + w;
    const float*  __restrict__ Pq = g_q + b * TT * HH + c4;
    const float*  __restrict__ Pk = g_k + b * TT * HH + c4;
    const float4* __restrict__ Pg = g_gates + b * TT * HH + r;
    float* __restrict__ Dst = g_h + b * TT * HH + r;

    float4 qb[8], kb[8], gb[8];
    #pragma unroll
    for (int s = 0; s < 8; s++) {
        qb[s] = *(const float4*)(Pq + s * HH);
        kb[s] = *(const float4*)(Pk + s * HH);
        gb[s] = Pg[s * HH];
    }
    float C0 = 0.f, C1 = 0.f, C2 = 0.f, C3 = 0.f;

    for (int gI = 0; gI < 64; gI++) {
        float dp[8];
        #pragma unroll
        for (int s = 0; s < 8; s++) {
            float4 q = qb[s], k = kb[s], gg = gb[s];   // gg = (i, f, v, o)[r]
            // h_tilde partial with OLD C, pre-scaled by o[r]
            dp[s] = gg.w * (C0 * q.x + C1 * q.y + C2 * q.z + C3 * q.w);
            const float aa = gg.x * gg.z;              // i[r] * v[r]
            C0 = fmaf(gg.y, C0, aa * k.x);
            C1 = fmaf(gg.y, C1, aa * k.y);
            C2 = fmaf(gg.y, C2, aa * k.z);
            C3 = fmaf(gg.y, C3, aa * k.w);
            if (gI < 63) {
                const int off = (gI * 8 + s + 8) * HH;
                qb[s] = *(const float4*)(Pq + off);
                kb[s] = *(const float4*)(Pk + off);
                gb[s] = Pg[off];
            }
        }
        // 8 independent butterfly reductions (pipelined, level-synchronous)
        #pragma unroll
        for (int o = 16; o > 0; o >>= 1)
            #pragma unroll
            for (int s = 0; s < 8; s++)
                dp[s] += __shfl_xor_sync(0xffffffffu, dp[s], o);
        if (lane == 0) {
            #pragma unroll
            for (int s = 0; s < 8; s++)
                Dst[(gI * 8 + s) * HH] = dp[s];        // unnormalized
        }
    }
}

// ---------------- final normalization ----------------
__global__ void normalize_kernel(float* __restrict__ out)
{
    const int idx = blockIdx.x * 256 + threadIdx.x;
    out[idx] = g_h[idx] * g_rden[idx >> 7];
}

// ---------------- launcher ----------------
extern "C" void kernel_launch(void* const* d_in, const int* in_sizes, int n_in,
                              void* d_out, int out_size)
{
    const float* x  = (const float*)d_in[0];
    const float* Wq = (const float*)d_in[1];
    const float* Wk = (const float*)d_in[2];
    const float* Wv = (const float*)d_in[3];
    const float* Wi = (const float*)d_in[4];
    const float* Wf = (const float*)d_in[5];
    const float* Wo = (const float*)d_in[6];
    const float* bq = (const float*)d_in[7];
    const float* bk = (const float*)d_in[8];
    const float* bv = (const float*)d_in[9];
    const float* bi = (const float*)d_in[10];
    const float* bf = (const float*)d_in[11];
    const float* bo = (const float*)d_in[12];
    float* out = (float*)d_out;

    const int total_w = LAYERS * 6 * HH * HH;
    transpose_w_kernel<<<(total_w + 255) / 256, 256>>>(Wq, Wk, Wv, Wi, Wf, Wo);

    dim3 ggrid(MM / 64, 6);
    dim3 sgrid(17, BB);

    // layer 0
    proj_gemm_kernel<<<ggrid, 128>>>(x, 0, bq, bk, bv, bi, bf, bo);
    scan_kernel<<<sgrid, 256>>>();                        // g_h (raw) + g_rden
    // layer 1 (normalization of layer-0 output fused into A-load)
    proj_gemm_kernel<<<ggrid, 128>>>(nullptr, 1, bq, bk, bv, bi, bf, bo);
    scan_kernel<<<sgrid, 256>>>();                        // g_h (raw) + g_rden
    // final normalize into d_out
    normalize_kernel<<<(MM * HH) / 256, 256>>>(out);
}

// round 10
// speedup vs baseline: 1.7060x; 1.7060x over previous
#include <cuda_runtime.h>
#include <math.h>

#define LAYERS 2
#define BB 8
#define TT 512
#define HH 128
#define MM (BB*TT)   // 4096 rows

// ---------------- device scratch ----------------
__device__ float  g_Wt[LAYERS][6][HH*HH];  // transposed weights [l][p][d][h]
__device__ float  g_q[MM*HH];              // q
__device__ float  g_k[MM*HH];              // k / sqrt(H)
__device__ float  g_i[MM*HH];              // exp(i)   (planar, for den warp)
__device__ float  g_f[MM*HH];              // sigm(f)  (planar, for den warp)
__device__ float4 g_gates[MM*HH];          // packed (i, f, v, o) per (m, h)
__device__ float  g_h[MM*HH];              // UNNORMALIZED hidden (o * C.q)
__device__ float  g_rden[MM];              // 1 / max(|n.q|, 1) per (b,t)

// ---------------- weight transpose ----------------
__global__ void transpose_w_kernel(const float* __restrict__ Wq, const float* __restrict__ Wk,
                                   const float* __restrict__ Wv, const float* __restrict__ Wi,
                                   const float* __restrict__ Wf, const float* __restrict__ Wo)
{
    int idx = blockIdx.x * blockDim.x + threadIdx.x;
    const int total = LAYERS * 6 * HH * HH;
    if (idx >= total) return;
    int l   = idx / (6 * HH * HH);
    int rem = idx - l * 6 * HH * HH;
    int p   = rem / (HH * HH);
    int e   = rem - p * (HH * HH);
    int d   = e >> 7;
    int h   = e & 127;
    const float* W = (p == 0) ? Wq : (p == 1) ? Wk : (p == 2) ? Wv
                   : (p == 3) ? Wi : (p == 4) ? Wf : Wo;
    g_Wt[l][p][d * HH + h] = W[l * HH * HH + h * HH + d];
}

// ---------------- projection GEMM + bias + activation (round-6 exact) ----------------
// 64x128 tile, BK=8, 128 threads, 8x8 microtile. grid (MM/64, 6) = 384 CTAs.
// For layer 1 (X==nullptr) the A operand is g_h scaled by g_rden (fused norm).
__global__ __launch_bounds__(128) void proj_gemm_kernel(
    const float* __restrict__ X, int layer,
    const float* __restrict__ bq, const float* __restrict__ bk,
    const float* __restrict__ bv, const float* __restrict__ bi,
    const float* __restrict__ bf, const float* __restrict__ bo)
{
    const float* __restrict__ Xp = X ? X : g_h;
    const int p  = blockIdx.y;
    const int m0 = blockIdx.x * 64;
    const float* __restrict__ Wt = g_Wt[layer][p];

    __shared__ float As[8][64];
    __shared__ float Bs[8][128];

    const int tid = threadIdx.x;
    const int tx = tid & 15;          // 16 col groups (x8 = 128)
    const int ty = tid >> 4;          // 8 row groups  (x8 = 64)
    const int lm = tid >> 1;          // 0..63 : M row for X load
    const int lk = (tid & 1) << 2;    // 0 or 4
    const int wh = (tid & 15) << 3;   // 0..120
    const int wk = tid >> 4;          // 0..7

    const float rd = X ? 1.0f : g_rden[m0 + lm];  // fused normalization of layer-0 output

    float acc[8][8];
    #pragma unroll
    for (int i = 0; i < 8; i++)
        #pragma unroll
        for (int j = 0; j < 8; j++) acc[i][j] = 0.0f;

    for (int k0 = 0; k0 < HH; k0 += 8) {
        float4 xa = *(const float4*)(Xp + (m0 + lm) * HH + k0 + lk);
        float4 wa = *(const float4*)(Wt + (k0 + wk) * HH + wh);
        float4 wb = *(const float4*)(Wt + (k0 + wk) * HH + wh + 4);
        As[lk + 0][lm] = xa.x * rd;
        As[lk + 1][lm] = xa.y * rd;
        As[lk + 2][lm] = xa.z * rd;
        As[lk + 3][lm] = xa.w * rd;
        *(float4*)(&Bs[wk][wh])     = wa;
        *(float4*)(&Bs[wk][wh + 4]) = wb;
        __syncthreads();
        #pragma unroll
        for (int kk = 0; kk < 8; kk++) {
            float a[8], b[8];
            *(float4*)(a)     = *(const float4*)(&As[kk][ty * 8]);
            *(float4*)(a + 4) = *(const float4*)(&As[kk][ty * 8 + 4]);
            *(float4*)(b)     = *(const float4*)(&Bs[kk][tx * 8]);
            *(float4*)(b + 4) = *(const float4*)(&Bs[kk][tx * 8 + 4]);
            #pragma unroll
            for (int i = 0; i < 8; i++)
                #pragma unroll
                for (int j = 0; j < 8; j++)
                    acc[i][j] = fmaf(a[i], b[j], acc[i][j]);
        }
        __syncthreads();
    }

    const float* __restrict__ bias =
        (p == 0) ? bq : (p == 1) ? bk : (p == 2) ? bv
      : (p == 3) ? bi : (p == 4) ? bf : bo;
    const float kscale = 0.088388347648318447f;  // 1/sqrt(128)

    #pragma unroll
    for (int i = 0; i < 8; i++) {
        const int m = m0 + ty * 8 + i;
        #pragma unroll
        for (int j = 0; j < 8; j++) {
            const int h = tx * 8 + j;
            float v = acc[i][j] + bias[layer * HH + h];
            const int e = m * HH + h;
            if (p == 0) {
                g_q[e] = v;
            } else if (p == 1) {
                g_k[e] = v * kscale;
            } else if (p == 2) {
                g_gates[e].z = v;                       // v
            } else if (p == 3) {
                v = expf(v);
                g_i[e] = v; g_gates[e].x = v;           // i
            } else if (p == 4) {
                v = 1.0f / (1.0f + expf(-v));
                g_f[e] = v; g_gates[e].y = v;           // f
            } else {
                v = 1.0f / (1.0f + expf(-v));
                g_gates[e].w = v;                       // o
            }
        }
    }
}

// Merge-tree reduction of 8 per-lane values over 32 lanes: 9 SHFL total.
// On return, every lane holds the full sum of value index idx = (lane>>2)&7,
// where idx bit2 = lane bit4, bit1 = lane bit3, bit0 = lane bit2.
__device__ __forceinline__ float reduce8_merge(const float dp[8], int lane)
{
    const bool h4 = (lane & 16) != 0;
    float x0, x1, x2, x3;
    {
        float a, b;
        a = h4 ? dp[4] : dp[0]; b = h4 ? dp[0] : dp[4];
        x0 = a + __shfl_xor_sync(0xffffffffu, b, 16);
        a = h4 ? dp[5] : dp[1]; b = h4 ? dp[1] : dp[5];
        x1 = a + __shfl_xor_sync(0xffffffffu, b, 16);
        a = h4 ? dp[6] : dp[2]; b = h4 ? dp[2] : dp[6];
        x2 = a + __shfl_xor_sync(0xffffffffu, b, 16);
        a = h4 ? dp[7] : dp[3]; b = h4 ? dp[3] : dp[7];
        x3 = a + __shfl_xor_sync(0xffffffffu, b, 16);
    }
    const bool h3 = (lane & 8) != 0;
    float z0, z1;
    {
        float a, b;
        a = h3 ? x2 : x0; b = h3 ? x0 : x2;
        z0 = a + __shfl_xor_sync(0xffffffffu, b, 8);
        a = h3 ? x3 : x1; b = h3 ? x1 : x3;
        z1 = a + __shfl_xor_sync(0xffffffffu, b, 8);
    }
    const bool h2 = (lane & 4) != 0;
    float w;
    {
        float a = h2 ? z1 : z0, b = h2 ? z0 : z1;
        w = a + __shfl_xor_sync(0xffffffffu, b, 4);
    }
    w += __shfl_xor_sync(0xffffffffu, w, 2);
    w += __shfl_xor_sync(0xffffffffu, w, 1);
    return w;
}

// ---------------- barrier-free mLSTM scan ----------------
// grid (17, 8), block 256 (8 warps). NO smem, NO __syncthreads.
//  bx < 16 : warp w owns row r = bx*8 + w of batch b; lane owns C[r][c4..c4+3].
//            h_tilde partials batch-reduced 8 steps at a time via the 9-SHFL
//            merge tree; 8 lanes store the 8 results (one STG each).
//  bx == 16: warp 0 runs the denominator recurrence, same reduction.
__global__ __launch_bounds__(256) void scan_kernel()
{
    const int b    = blockIdx.y;
    const int w    = threadIdx.x >> 5;
    const int lane = threadIdx.x & 31;
    const int c4   = lane << 2;
    const int sidx = (lane >> 2) & 7;          // value index this lane ends up with
    const bool wl  = (lane & 3) == 0;          // one writer lane per quad

    if (blockIdx.x == 16) {
        // ---- denominator warp ----
        if (w != 0) return;
        const float* __restrict__ Pq = g_q + b * TT * HH + c4;
        const float* __restrict__ Pk = g_k + b * TT * HH + c4;
        const float* __restrict__ Pi = g_i + b * TT * HH + c4;
        const float* __restrict__ Pf = g_f + b * TT * HH + c4;
        float* __restrict__ Dr = g_rden + b * TT;

        float4 qb[8], kb[8], ib[8], fb[8];
        #pragma unroll
        for (int s = 0; s < 8; s++) {
            qb[s] = *(const float4*)(Pq + s * HH);
            kb[s] = *(const float4*)(Pk + s * HH);
            ib[s] = *(const float4*)(Pi + s * HH);
            fb[s] = *(const float4*)(Pf + s * HH);
        }
        float n0 = 0.f, n1 = 0.f, n2 = 0.f, n3 = 0.f;

        for (int gI = 0; gI < 64; gI++) {
            float pd[8];
            #pragma unroll
            for (int s = 0; s < 8; s++) {
                float4 q = qb[s], k = kb[s], ii = ib[s], ff = fb[s];
                pd[s] = n0 * q.x + n1 * q.y + n2 * q.z + n3 * q.w;  // uses OLD n
                n0 = fmaf(ff.x, n0, ii.x * k.x);
                n1 = fmaf(ff.y, n1, ii.y * k.y);
                n2 = fmaf(ff.z, n2, ii.z * k.z);
                n3 = fmaf(ff.w, n3, ii.w * k.w);
                if (gI < 63) {
                    const int off = (gI * 8 + s + 8) * HH;
                    qb[s] = *(const float4*)(Pq + off);
                    kb[s] = *(const float4*)(Pk + off);
                    ib[s] = *(const float4*)(Pi + off);
                    fb[s] = *(const float4*)(Pf + off);
                }
            }
            const float tot = reduce8_merge(pd, lane);
            if (wl) Dr[gI * 8 + sidx] = 1.0f / fmaxf(fabsf(tot), 1.0f);
        }
        return;
    }

    // ---- row warps ----
    const int r = blockIdx.x * 8 + w;
    const float*  __restrict__ Pq = g_q + b * TT * HH + c4;
    const float*  __restrict__ Pk = g_k + b * TT * HH + c4;
    const float4* __restrict__ Pg = g_gates + b * TT * HH + r;
    float* __restrict__ Dst = g_h + b * TT * HH + r;

    float4 qb[8], kb[8], gb[8];
    #pragma unroll
    for (int s = 0; s < 8; s++) {
        qb[s] = *(const float4*)(Pq + s * HH);
        kb[s] = *(const float4*)(Pk + s * HH);
        gb[s] = Pg[s * HH];
    }
    float C0 = 0.f, C1 = 0.f, C2 = 0.f, C3 = 0.f;

    for (int gI = 0; gI < 64; gI++) {
        float dp[8];
        #pragma unroll
        for (int s = 0; s < 8; s++) {
            float4 q = qb[s], k = kb[s], gg = gb[s];   // gg = (i, f, v, o)[r]
            // h_tilde partial with OLD C, pre-scaled by o[r]
            dp[s] = gg.w * (C0 * q.x + C1 * q.y + C2 * q.z + C3 * q.w);
            const float aa = gg.x * gg.z;              // i[r] * v[r]
            C0 = fmaf(gg.y, C0, aa * k.x);
            C1 = fmaf(gg.y, C1, aa * k.y);
            C2 = fmaf(gg.y, C2, aa * k.z);
            C3 = fmaf(gg.y, C3, aa * k.w);
            if (gI < 63) {
                const int off = (gI * 8 + s + 8) * HH;
                qb[s] = *(const float4*)(Pq + off);
                kb[s] = *(const float4*)(Pk + off);
                gb[s] = Pg[off];
            }
        }
        const float tot = reduce8_merge(dp, lane);
        if (wl) Dst[(gI * 8 + sidx) * HH] = tot;       // unnormalized
    }
}

// ---------------- final normalization ----------------
__global__ void normalize_kernel(float* __restrict__ out)
{
    const int idx = blockIdx.x * 256 + threadIdx.x;
    out[idx] = g_h[idx] * g_rden[idx >> 7];
}

// ---------------- launcher ----------------
extern "C" void kernel_launch(void* const* d_in, const int* in_sizes, int n_in,
                              void* d_out, int out_size)
{
    const float* x  = (const float*)d_in[0];
    const float* Wq = (const float*)d_in[1];
    const float* Wk = (const float*)d_in[2];
    const float* Wv = (const float*)d_in[3];
    const float* Wi = (const float*)d_in[4];
    const float* Wf = (const float*)d_in[5];
    const float* Wo = (const float*)d_in[6];
    const float* bq = (const float*)d_in[7];
    const float* bk = (const float*)d_in[8];
    const float* bv = (const float*)d_in[9];
    const float* bi = (const float*)d_in[10];
    const float* bf = (const float*)d_in[11];
    const float* bo = (const float*)d_in[12];
    float* out = (float*)d_out;

    const int total_w = LAYERS * 6 * HH * HH;
    transpose_w_kernel<<<(total_w + 255) / 256, 256>>>(Wq, Wk, Wv, Wi, Wf, Wo);

    dim3 ggrid(MM / 64, 6);
    dim3 sgrid(17, BB);

    // layer 0
    proj_gemm_kernel<<<ggrid, 128>>>(x, 0, bq, bk, bv, bi, bf, bo);
    scan_kernel<<<sgrid, 256>>>();                        // g_h (raw) + g_rden
    // layer 1 (normalization of layer-0 output fused into A-load)
    proj_gemm_kernel<<<ggrid, 128>>>(nullptr, 1, bq, bk, bv, bi, bf, bo);
    scan_kernel<<<sgrid, 256>>>();                        // g_h (raw) + g_rden
    // final normalize into d_out
    normalize_kernel<<<(MM * HH) / 256, 256>>>(out);
}